// round 15
// baseline (speedup 1.0000x reference)
#include <cuda_runtime.h>
#include <stdint.h>

#define N_NODES 100000
#define DEG 12
#define CH 64
#define NREL 8

#define THREADS 384                 // 8 producer warps + 4 consumer warps
#define NPROD 8
#define CHUNK 16
#define NCHUNKS 16
#define M_CTA (CHUNK * NCHUNKS)     // 256 nodes per CTA
#define GRID ((N_NODES + M_CTA - 1) / M_CTA)   // 391

#define SROW 68                     // padded row stride (floats), conflict-free
#define S_BUF_FLOATS (NREL * CHUNK * SROW)     // 8704 floats = 34816 B
#define S_BYTES (2 * S_BUF_FLOATS * 4)         // 69632
#define W_UINT4 (NREL * 8 * 4 * 32)            // 8192 uint4
#define W_BYTES (W_UINT4 * 16)                 // 131072
#define SMEM_BYTES (S_BYTES + W_BYTES)         // 200704

// B fragments, /12 folded, tf32, uint4-packed (staged to smem):
// g_wt4[((rel*8+kt)*4+nq)*32 + lane]; word w: n = nq*16+(w>>1)*8+lane/4, k = kt*8+lane%4+4*(w&1)
__device__ uint4 g_wt4[W_UINT4];

__device__ __forceinline__ uint32_t f2tf32(float f) {
    uint32_t r;
    asm("cvt.rna.tf32.f32 %0, %1;" : "=r"(r) : "f"(f));
    return r;
}

__device__ __forceinline__ void mma_tf32(float* d, const uint32_t* a, uint32_t b0, uint32_t b1) {
    asm volatile("mma.sync.aligned.m16n8k8.row.col.f32.tf32.tf32.f32 "
                 "{%0,%1,%2,%3}, {%4,%5,%6,%7}, {%8,%9}, {%0,%1,%2,%3};"
                 : "+f"(d[0]), "+f"(d[1]), "+f"(d[2]), "+f"(d[3])
                 : "r"(a[0]), "r"(a[1]), "r"(a[2]), "r"(a[3]), "r"(b0), "r"(b1));
}

// named barriers: 1,2 = FULL[buf]; 3,4 = FREE[buf]; 5 = consumer-internal (W staged)
#define BAR_SYNC(id, cnt)   asm volatile("bar.sync %0, %1;"   :: "r"(id), "r"(cnt) : "memory")
#define BAR_ARRIVE(id, cnt) asm volatile("bar.arrive %0, %1;" :: "r"(id), "r"(cnt) : "memory")

__global__ __launch_bounds__(THREADS, 1)
void rgcn_ws_kernel(const float* __restrict__ x,
                    const void* __restrict__ ptrv,
                    const void* __restrict__ idxv,
                    const void* __restrict__ etv,
                    float* __restrict__ out)
{
    extern __shared__ float smem[];          // [2][NREL][CHUNK][SROW] then W
    uint4* Wsm = (uint4*)((char*)smem + S_BYTES);

    const int tid = threadIdx.x, wid = tid >> 5, lane = tid & 31;
    const int blk = blockIdx.x;
    const bool is64 = (((const int*)ptrv)[1] == 0);   // int64 -> high half of ptr[0]=0

    if (wid < NPROD) {
        // ================= PRODUCER: gather-sum 2 nodes per chunk =================
        const int hl = lane & 15;
        const int half = lane >> 4;

        // prefetch all chunks' edge metadata (packed = src | rel<<24; sentinel rel=255)
        uint32_t packed[NCHUNKS];
        #pragma unroll
        for (int c = 0; c < NCHUNKS; ++c) {
            const int node = blk * M_CTA + c * CHUNK + wid * 2 + half;
            uint32_t p = 0xFFu << 24;
            if (hl < DEG && node < N_NODES) {
                uint32_t s, r;
                if (is64) {
                    s = (uint32_t)((const long long*)idxv)[(size_t)node * DEG + hl];
                    r = (uint32_t)((const long long*)etv)[(size_t)node * DEG + hl];
                } else {
                    s = ((const uint32_t*)idxv)[node * DEG + hl];
                    r = ((const uint32_t*)etv)[node * DEG + hl];
                }
                p = s | (r << 24);
            }
            packed[c] = p;
        }

        const float* xl = x + 2 * lane;    // this lane's channel pair
        const int mA = wid * 2, mB = mA + 1;

        #pragma unroll 1
        for (int c = 0; c < NCHUNKS; ++c) {
            // issue all 24 row loads (both nodes) BEFORE the free-wait: latency
            // is absorbed by the barrier wait below.
            uint32_t rlA[DEG], rlB[DEG];
            float2 vA[DEG], vB[DEG];
            #pragma unroll
            for (int e = 0; e < DEG; ++e) {
                const uint32_t sa = __shfl_sync(0xffffffffu, packed[c], e);
                const uint32_t sb = __shfl_sync(0xffffffffu, packed[c], 16 + e);
                rlA[e] = sa >> 24;
                rlB[e] = sb >> 24;
                vA[e] = *(const float2*)(xl + (size_t)(sa & 0x00FFFFFFu) * CH);
                vB[e] = *(const float2*)(xl + (size_t)(sb & 0x00FFFFFFu) * CH);
            }

            BAR_SYNC(3 + (c & 1), THREADS);          // wait buffer free

            // demux: rel warp-uniform per edge -> predicated adds
            float2 aA[NREL], aB[NREL];
            #pragma unroll
            for (int r = 0; r < NREL; ++r) { aA[r] = make_float2(0.f, 0.f); aB[r] = make_float2(0.f, 0.f); }
            #pragma unroll
            for (int e = 0; e < DEG; ++e) {
                #pragma unroll
                for (int r = 0; r < NREL; ++r) {
                    if (rlA[e] == (uint32_t)r) { aA[r].x += vA[e].x; aA[r].y += vA[e].y; }
                    if (rlB[e] == (uint32_t)r) { aB[r].x += vB[e].x; aB[r].y += vB[e].y; }
                }
            }

            // store tf32-converted sums into this buffer
            float* Sb = smem + (c & 1) * S_BUF_FLOATS;
            #pragma unroll
            for (int r = 0; r < NREL; ++r) {
                uint2 oA, oB;
                oA.x = f2tf32(aA[r].x); oA.y = f2tf32(aA[r].y);
                oB.x = f2tf32(aB[r].x); oB.y = f2tf32(aB[r].y);
                *(uint2*)&Sb[(size_t)(r * CHUNK + mA) * SROW + 2 * lane] = oA;
                *(uint2*)&Sb[(size_t)(r * CHUNK + mB) * SROW + 2 * lane] = oB;
            }

            asm volatile("membar.cta;" ::: "memory");  // STS visible before arrive
            BAR_ARRIVE(1 + (c & 1), THREADS);          // signal buffer full
        }
    } else {
        // ================= CONSUMER: MMA over 16-col n-slice =================
        const int cw = wid - NPROD;                    // 0..3 -> cols [cw*16, cw*16+16)
        const int ct = tid - NPROD * 32;               // 0..127

        // both buffers start free
        BAR_ARRIVE(3, THREADS);
        BAR_ARRIVE(4, THREADS);

        // stage W (131072 B = 8192 uint4) into smem: 64 iters x 128 threads
        #pragma unroll
        for (int i = 0; i < W_UINT4 / 128; ++i)
            Wsm[ct + i * 128] = g_wt4[ct + i * 128];
        BAR_SYNC(5, 128);                              // consumers see full W

        const int arow0 = (lane >> 2) * SROW + (lane & 3);

        #pragma unroll 1
        for (int c = 0; c < NCHUNKS; ++c) {
            BAR_SYNC(1 + (c & 1), THREADS);            // wait buffer full
            const float* Sb = smem + (c & 1) * S_BUF_FLOATS;

            float d[2][4];
            #pragma unroll
            for (int h = 0; h < 2; ++h)
                #pragma unroll
                for (int q = 0; q < 4; ++q) d[h][q] = 0.f;

            #pragma unroll
            for (int rel = 0; rel < NREL; ++rel) {
                const uint32_t* Sr = (const uint32_t*)(Sb + (size_t)rel * CHUNK * SROW);
                #pragma unroll
                for (int kt = 0; kt < 8; ++kt) {
                    uint32_t a[4];
                    a[0] = Sr[arow0 + kt * 8];
                    a[1] = Sr[arow0 + 8 * SROW + kt * 8];
                    a[2] = Sr[arow0 + kt * 8 + 4];
                    a[3] = Sr[arow0 + 8 * SROW + kt * 8 + 4];
                    const uint4 b = Wsm[((rel * 8 + kt) * 4 + cw) * 32 + lane];
                    mma_tf32(d[0], a, b.x, b.y);
                    mma_tf32(d[1], a, b.z, b.w);
                }
            }

            // store this chunk's 16x16 block (normalization folded into W)
            const int row = blk * M_CTA + c * CHUNK + (lane >> 2);
            #pragma unroll
            for (int h = 0; h < 2; ++h) {
                const int col = cw * 16 + h * 8 + 2 * (lane & 3);
                if (row < N_NODES)
                    *(float2*)&out[(size_t)row * CH + col] = make_float2(d[h][0], d[h][1]);
                if (row + 8 < N_NODES)
                    *(float2*)&out[(size_t)(row + 8) * CH + col] = make_float2(d[h][2], d[h][3]);
            }

            BAR_ARRIVE(3 + (c & 1), THREADS);          // buffer free again
        }
    }
}

// ---- weight transform: transpose, /12 fold, tf32, uint4-fragment order ----
__global__ void wt_kernel(const float* __restrict__ lin)
{
    const int i = blockIdx.x * blockDim.x + threadIdx.x;   // 0..32767
    if (i < NREL * 8 * 4 * 32 * 4) {
        const int rel  = i >> 12;
        const int kt   = (i >> 9) & 7;
        const int nq   = (i >> 7) & 3;
        const int lane = (i >> 2) & 31;
        const int w    = i & 3;
        const int n = nq * 16 + ((w >> 1) << 3) + (lane >> 2);
        const int k = kt * 8 + (lane & 3) + 4 * (w & 1);
        ((uint32_t*)g_wt4)[i] = f2tf32(lin[((size_t)rel * CH + k) * CH + n] * (1.0f / 12.0f));
    }
}

extern "C" void kernel_launch(void* const* d_in, const int* in_sizes, int n_in,
                              void* d_out, int out_size)
{
    const float* x   = (const float*)d_in[0];
    const float* lin = (const float*)d_in[1];
    const void*  ptr = d_in[2];
    const void*  idx = d_in[3];
    const void*  et  = d_in[4];
    float* out = (float*)d_out;
    (void)in_sizes; (void)n_in; (void)out_size;

    cudaFuncSetAttribute(rgcn_ws_kernel,
                         cudaFuncAttributeMaxDynamicSharedMemorySize, SMEM_BYTES);

    wt_kernel<<<(NREL * 8 * 4 * 32 * 4 + 255) / 256, 256>>>(lin);
    rgcn_ws_kernel<<<GRID, THREADS, SMEM_BYTES>>>(x, ptr, idx, et, out);
}

// round 16
// speedup vs baseline: 2.9425x; 2.9425x over previous
#include <cuda_runtime.h>
#include <stdint.h>

#define N_NODES 100000
#define DEG 12
#define CH 64
#define NREL 8

#define THREADS 256
#define M_CTA 128
#define CHUNK 32
#define NCHUNK (M_CTA / CHUNK)                 // 4
#define GRID ((N_NODES + M_CTA - 1) / M_CTA)   // 782

#define SROW 68                                 // padded row stride (floats), conflict-free
#define S_REL (CHUNK * SROW)                    // 2176 floats per relation tile
#define SMEM_BYTES (NREL * S_REL * 4)           // 69632 B -> 2 CTAs/SM

// B fragments, repacked for uint4 loads, /12 folded, tf32:
// g_wt4[((rel*8+kt)*4+nq)*32 + lane] = {nt0.b0, nt0.b1, nt1.b0, nt1.b1}
//   word w: n = nq*16 + (w>>1)*8 + lane/4 ; k = kt*8 + lane%4 + 4*(w&1)
__device__ uint4 g_wt4[NREL * 8 * 4 * 32];

__device__ __forceinline__ uint32_t f2tf32(float f) {
    uint32_t r;
    asm("cvt.rna.tf32.f32 %0, %1;" : "=r"(r) : "f"(f));
    return r;
}

__device__ __forceinline__ void mma_tf32(float* d, const uint32_t* a, uint32_t b0, uint32_t b1) {
    asm volatile("mma.sync.aligned.m16n8k8.row.col.f32.tf32.tf32.f32 "
                 "{%0,%1,%2,%3}, {%4,%5,%6,%7}, {%8,%9}, {%0,%1,%2,%3};"
                 : "+f"(d[0]), "+f"(d[1]), "+f"(d[2]), "+f"(d[3])
                 : "r"(a[0]), "r"(a[1]), "r"(a[2]), "r"(a[3]), "r"(b0), "r"(b1));
}

// issue 12 independent row loads for one node (jq = which half of the packed word)
__device__ __forceinline__ void load_rows(float2* dst, uint32_t pk, int jq, const float* xl) {
    #pragma unroll
    for (int e = 0; e < DEG; ++e) {
        const uint32_t sel = __shfl_sync(0xffffffffu, pk, (jq << 4) + e);
        dst[e] = *(const float2*)(xl + (size_t)(sel & 0x00FFFFFFu) * CH);
    }
}

// demux one node's 12 rows into per-relation sums, cvt to tf32, store to S
__device__ __forceinline__ void demux_sts(const float2* v, uint32_t pk, int jq, int m,
                                          int lane, float* S) {
    float2 acc[NREL];
    #pragma unroll
    for (int r = 0; r < NREL; ++r) acc[r] = make_float2(0.f, 0.f);
    #pragma unroll
    for (int e = 0; e < DEG; ++e) {
        const uint32_t rl = __shfl_sync(0xffffffffu, pk, (jq << 4) + e) >> 24;
        #pragma unroll
        for (int r = 0; r < NREL; ++r)
            if (rl == (uint32_t)r) { acc[r].x += v[e].x; acc[r].y += v[e].y; }
    }
    #pragma unroll
    for (int r = 0; r < NREL; ++r) {
        uint2 o;
        o.x = f2tf32(acc[r].x);
        o.y = f2tf32(acc[r].y);
        *(uint2*)&S[(size_t)r * S_REL + m * SROW + 2 * lane] = o;
    }
}

__global__ __launch_bounds__(THREADS, 2)
void rgcn_kernel(const float* __restrict__ x,
                 const void* __restrict__ ptrv,
                 const void* __restrict__ idxv,
                 const void* __restrict__ etv,
                 float* __restrict__ out)
{
    extern __shared__ float S[];     // [NREL][CHUNK][SROW], tf32 bit patterns

    const int tid = threadIdx.x, wid = tid >> 5, lane = tid & 31;
    const int blk = blockIdx.x;
    const bool is64 = (((const int*)ptrv)[1] == 0);   // int64 -> high half of ptr[0]=0

    // phase-2 warp tiling: 2 m-tiles(16) x 4 n-groups(16) over the 32x64 chunk
    const int mt = wid & 1, nh = wid >> 1;
    const int arow = (mt * 16 + (lane >> 2)) * SROW + (lane & 3);

    const float* xl = x + 2 * lane;   // this lane's channel pair

    // ---- hoist all chunks' edge metadata; extra sentinel row for the tail prefetch ----
    // packed[c][q]: lanes 0-11 node (4*wid+2q), lanes 16-27 node (4*wid+2q+1)
    // packed = src | rel<<24 ; sentinel rel=255 (never demuxed), src 0 (safe load)
    uint32_t packed[NCHUNK + 1][2];
    {
        const int hl = lane & 15;
        #pragma unroll
        for (int c = 0; c < NCHUNK; ++c) {
            #pragma unroll
            for (int q = 0; q < 2; ++q) {
                const int node = blk * M_CTA + c * CHUNK + wid * 4 + 2 * q + (lane >> 4);
                uint32_t p = 0xFFu << 24;
                if (hl < DEG && node < N_NODES) {
                    uint32_t s, r;
                    if (is64) {
                        s = (uint32_t)((const long long*)idxv)[(size_t)node * DEG + hl];
                        r = (uint32_t)((const long long*)etv)[(size_t)node * DEG + hl];
                    } else {
                        s = ((const uint32_t*)idxv)[node * DEG + hl];
                        r = ((const uint32_t*)etv)[node * DEG + hl];
                    }
                    p = s | (r << 24);
                }
                packed[c][q] = p;
            }
        }
        packed[NCHUNK][0] = 0xFFu << 24;
        packed[NCHUNK][1] = 0xFFu << 24;
    }

    // ---- prologue: prefetch (chunk 0, node 0); stays in flight until first demux ----
    float2 v[DEG];
    load_rows(v, packed[0][0], 0, xl);

    #pragma unroll 1
    for (int chunk = 0; chunk < NCHUNK; ++chunk) {
        // ====== phase 1: pipelined gather (issue j+1 loads before demuxing j) ======
        const int m0 = wid * 4;
        float2 w0[DEG], w1[DEG], w2[DEG];

        load_rows(w0, packed[chunk][0], 1, xl);            // (c,1)
        demux_sts(v, packed[chunk][0], 0, m0 + 0, lane, S);

        load_rows(w1, packed[chunk][1], 0, xl);            // (c,2)
        demux_sts(w0, packed[chunk][0], 1, m0 + 1, lane, S);

        load_rows(w2, packed[chunk][1], 1, xl);            // (c,3)
        demux_sts(w1, packed[chunk][1], 0, m0 + 2, lane, S);

        load_rows(v, packed[chunk + 1][0], 0, xl);         // (c+1,0) — flies across MMA
        demux_sts(w2, packed[chunk][1], 1, m0 + 3, lane, S);

        __syncthreads();

        // ================= phase 2: D[32x64] = sum_r S_r @ Wt_r =================
        float d[2][4];
        #pragma unroll
        for (int nt = 0; nt < 2; ++nt)
            #pragma unroll
            for (int c = 0; c < 4; ++c) d[nt][c] = 0.f;

        #pragma unroll
        for (int rel = 0; rel < NREL; ++rel) {
            const uint32_t* Sr = (const uint32_t*)S + (size_t)rel * S_REL;
            #pragma unroll
            for (int kt = 0; kt < 8; ++kt) {
                uint32_t a[4];
                a[0] = Sr[arow + kt * 8];
                a[1] = Sr[arow + kt * 8 + 8 * SROW];
                a[2] = Sr[arow + kt * 8 + 4];
                a[3] = Sr[arow + kt * 8 + 8 * SROW + 4];
                const uint4 b = g_wt4[((rel * 8 + kt) * 4 + nh) * 32 + lane];
                mma_tf32(d[0], a, b.x, b.y);
                mma_tf32(d[1], a, b.z, b.w);
            }
        }

        // ---- epilogue for this chunk ----
        {
            const int row = blk * M_CTA + chunk * CHUNK + mt * 16 + (lane >> 2);
            #pragma unroll
            for (int nt = 0; nt < 2; ++nt) {
                const int col = nh * 16 + nt * 8 + 2 * (lane & 3);
                if (row < N_NODES)
                    *(float2*)&out[(size_t)row * CH + col] = make_float2(d[nt][0], d[nt][1]);
                if (row + 8 < N_NODES)
                    *(float2*)&out[(size_t)(row + 8) * CH + col] = make_float2(d[nt][2], d[nt][3]);
            }
        }
        __syncthreads();   // S safe to overwrite next chunk
    }
}

// ---- weight transform: transpose, /12 fold, tf32, uint4-fragment order ----
__global__ void wt_kernel(const float* __restrict__ lin)
{
    const int i = blockIdx.x * blockDim.x + threadIdx.x;   // 0..32767
    if (i < NREL * 8 * 4 * 32 * 4) {
        const int rel  = i >> 12;
        const int kt   = (i >> 9) & 7;
        const int nq   = (i >> 7) & 3;
        const int lane = (i >> 2) & 31;
        const int w    = i & 3;
        const int n = nq * 16 + ((w >> 1) << 3) + (lane >> 2);
        const int k = kt * 8 + (lane & 3) + 4 * (w & 1);
        ((uint32_t*)g_wt4)[i] = f2tf32(lin[((size_t)rel * CH + k) * CH + n] * (1.0f / 12.0f));
    }
}

extern "C" void kernel_launch(void* const* d_in, const int* in_sizes, int n_in,
                              void* d_out, int out_size)
{
    const float* x   = (const float*)d_in[0];
    const float* lin = (const float*)d_in[1];
    const void*  ptr = d_in[2];
    const void*  idx = d_in[3];
    const void*  et  = d_in[4];
    float* out = (float*)d_out;
    (void)in_sizes; (void)n_in; (void)out_size;

    cudaFuncSetAttribute(rgcn_kernel,
                         cudaFuncAttributeMaxDynamicSharedMemorySize, SMEM_BYTES);

    wt_kernel<<<(NREL * 8 * 4 * 32 * 4 + 255) / 256, 256>>>(lin);
    rgcn_kernel<<<GRID, THREADS, SMEM_BYTES>>>(x, ptr, idx, et, out);
}

// round 17
// speedup vs baseline: 3.1101x; 1.0570x over previous
#include <cuda_runtime.h>
#include <stdint.h>

#define N_NODES 100000
#define DEG 12
#define CH 64
#define NREL 8

#define THREADS 256
#define M_CTA 64
#define CHUNK 32
#define NCHUNK (M_CTA / CHUNK)                 // 2
#define GRID ((N_NODES + M_CTA - 1) / M_CTA)   // 1563

#define SROW 68                                 // padded row stride (floats), conflict-free
#define S_REL (CHUNK * SROW)                    // 2176 floats per relation tile
#define SMEM_BYTES (NREL * S_REL * 4)           // 69632 B -> 2 CTAs/SM

// B fragments, repacked for uint4 loads, /12 folded, tf32:
// g_wt4[((rel*8+kt)*4+nq)*32 + lane] = {nt0.b0, nt0.b1, nt1.b0, nt1.b1}
//   word w: n = nq*16 + (w>>1)*8 + lane/4 ; k = kt*8 + lane%4 + 4*(w&1)
__device__ uint4 g_wt4[NREL * 8 * 4 * 32];

__device__ __forceinline__ uint32_t f2tf32(float f) {
    uint32_t r;
    asm("cvt.rna.tf32.f32 %0, %1;" : "=r"(r) : "f"(f));
    return r;
}

__device__ __forceinline__ void mma_tf32(float* d, const uint32_t* a, uint32_t b0, uint32_t b1) {
    asm volatile("mma.sync.aligned.m16n8k8.row.col.f32.tf32.tf32.f32 "
                 "{%0,%1,%2,%3}, {%4,%5,%6,%7}, {%8,%9}, {%0,%1,%2,%3};"
                 : "+f"(d[0]), "+f"(d[1]), "+f"(d[2]), "+f"(d[3])
                 : "r"(a[0]), "r"(a[1]), "r"(a[2]), "r"(a[3]), "r"(b0), "r"(b1));
}

// issue 12 independent row loads for one node (jq = which half of the packed word)
__device__ __forceinline__ void load_rows(float2* dst, uint32_t pk, int jq, const float* xl) {
    #pragma unroll
    for (int e = 0; e < DEG; ++e) {
        const uint32_t sel = __shfl_sync(0xffffffffu, pk, (jq << 4) + e);
        dst[e] = *(const float2*)(xl + (size_t)(sel & 0x00FFFFFFu) * CH);
    }
}

// demux one node's 12 rows into per-relation sums, cvt to tf32, store to S
__device__ __forceinline__ void demux_sts(const float2* v, uint32_t pk, int jq, int m,
                                          int lane, float* S) {
    float2 acc[NREL];
    #pragma unroll
    for (int r = 0; r < NREL; ++r) acc[r] = make_float2(0.f, 0.f);
    #pragma unroll
    for (int e = 0; e < DEG; ++e) {
        const uint32_t rl = __shfl_sync(0xffffffffu, pk, (jq << 4) + e) >> 24;
        #pragma unroll
        for (int r = 0; r < NREL; ++r)
            if (rl == (uint32_t)r) { acc[r].x += v[e].x; acc[r].y += v[e].y; }
    }
    #pragma unroll
    for (int r = 0; r < NREL; ++r) {
        uint2 o;
        o.x = f2tf32(acc[r].x);
        o.y = f2tf32(acc[r].y);
        *(uint2*)&S[(size_t)r * S_REL + m * SROW + 2 * lane] = o;
    }
}

__global__ __launch_bounds__(THREADS, 2)
void rgcn_kernel(const float* __restrict__ x,
                 const void* __restrict__ ptrv,
                 const void* __restrict__ idxv,
                 const void* __restrict__ etv,
                 float* __restrict__ out)
{
    extern __shared__ float S[];     // [NREL][CHUNK][SROW], tf32 bit patterns

    const int tid = threadIdx.x, wid = tid >> 5, lane = tid & 31;
    const int blk = blockIdx.x;
    const bool is64 = (((const int*)ptrv)[1] == 0);   // int64 -> high half of ptr[0]=0

    // phase-2 warp tiling: 2 m-tiles(16) x 4 n-groups(16) over the 32x64 chunk
    const int mt = wid & 1, nh = wid >> 1;
    const int arow = (mt * 16 + (lane >> 2)) * SROW + (lane & 3);

    const float* xl = x + 2 * lane;   // this lane's channel pair

    // ---- hoist all chunks' edge metadata; extra sentinel row for the tail prefetch ----
    // packed[c][q]: lanes 0-11 node (4*wid+2q), lanes 16-27 node (4*wid+2q+1)
    // packed = src | rel<<24 ; sentinel rel=255 (never demuxed), src 0 (safe load)
    uint32_t packed[NCHUNK + 1][2];
    {
        const int hl = lane & 15;
        #pragma unroll
        for (int c = 0; c < NCHUNK; ++c) {
            #pragma unroll
            for (int q = 0; q < 2; ++q) {
                const int node = blk * M_CTA + c * CHUNK + wid * 4 + 2 * q + (lane >> 4);
                uint32_t p = 0xFFu << 24;
                if (hl < DEG && node < N_NODES) {
                    uint32_t s, r;
                    if (is64) {
                        s = (uint32_t)((const long long*)idxv)[(size_t)node * DEG + hl];
                        r = (uint32_t)((const long long*)etv)[(size_t)node * DEG + hl];
                    } else {
                        s = ((const uint32_t*)idxv)[node * DEG + hl];
                        r = ((const uint32_t*)etv)[node * DEG + hl];
                    }
                    p = s | (r << 24);
                }
                packed[c][q] = p;
            }
        }
        packed[NCHUNK][0] = 0xFFu << 24;
        packed[NCHUNK][1] = 0xFFu << 24;
    }

    // ---- prologue: prefetch (chunk 0, node 0); stays in flight until first demux ----
    float2 v[DEG];
    load_rows(v, packed[0][0], 0, xl);

    #pragma unroll 1
    for (int chunk = 0; chunk < NCHUNK; ++chunk) {
        // ====== phase 1: pipelined gather (issue j+1 loads before demuxing j) ======
        const int m0 = wid * 4;
        float2 w0[DEG], w1[DEG], w2[DEG];

        load_rows(w0, packed[chunk][0], 1, xl);            // (c,1)
        demux_sts(v, packed[chunk][0], 0, m0 + 0, lane, S);

        load_rows(w1, packed[chunk][1], 0, xl);            // (c,2)
        demux_sts(w0, packed[chunk][0], 1, m0 + 1, lane, S);

        load_rows(w2, packed[chunk][1], 1, xl);            // (c,3)
        demux_sts(w1, packed[chunk][1], 0, m0 + 2, lane, S);

        load_rows(v, packed[chunk + 1][0], 0, xl);         // (c+1,0) — flies across MMA
        demux_sts(w2, packed[chunk][1], 1, m0 + 3, lane, S);

        __syncthreads();

        // ================= phase 2: D[32x64] = sum_r S_r @ Wt_r =================
        float d[2][4];
        #pragma unroll
        for (int nt = 0; nt < 2; ++nt)
            #pragma unroll
            for (int c = 0; c < 4; ++c) d[nt][c] = 0.f;

        #pragma unroll
        for (int rel = 0; rel < NREL; ++rel) {
            const uint32_t* Sr = (const uint32_t*)S + (size_t)rel * S_REL;
            #pragma unroll
            for (int kt = 0; kt < 8; ++kt) {
                uint32_t a[4];
                a[0] = Sr[arow + kt * 8];
                a[1] = Sr[arow + kt * 8 + 8 * SROW];
                a[2] = Sr[arow + kt * 8 + 4];
                a[3] = Sr[arow + kt * 8 + 8 * SROW + 4];
                const uint4 b = g_wt4[((rel * 8 + kt) * 4 + nh) * 32 + lane];
                mma_tf32(d[0], a, b.x, b.y);
                mma_tf32(d[1], a, b.z, b.w);
            }
        }

        // S fully consumed by MMA: release it for the next chunk's STS now, so the
        // epilogue's global stores overlap other warps' next-chunk demux.
        __syncthreads();

        // ---- epilogue for this chunk (registers -> gmem; no S access) ----
        {
            const int row = blk * M_CTA + chunk * CHUNK + mt * 16 + (lane >> 2);
            #pragma unroll
            for (int nt = 0; nt < 2; ++nt) {
                const int col = nh * 16 + nt * 8 + 2 * (lane & 3);
                if (row < N_NODES)
                    *(float2*)&out[(size_t)row * CH + col] = make_float2(d[nt][0], d[nt][1]);
                if (row + 8 < N_NODES)
                    *(float2*)&out[(size_t)(row + 8) * CH + col] = make_float2(d[nt][2], d[nt][3]);
            }
        }
    }
}

// ---- weight transform: transpose, /12 fold, tf32, uint4-fragment order ----
__global__ void wt_kernel(const float* __restrict__ lin)
{
    const int i = blockIdx.x * blockDim.x + threadIdx.x;   // 0..32767
    if (i < NREL * 8 * 4 * 32 * 4) {
        const int rel  = i >> 12;
        const int kt   = (i >> 9) & 7;
        const int nq   = (i >> 7) & 3;
        const int lane = (i >> 2) & 31;
        const int w    = i & 3;
        const int n = nq * 16 + ((w >> 1) << 3) + (lane >> 2);
        const int k = kt * 8 + (lane & 3) + 4 * (w & 1);
        ((uint32_t*)g_wt4)[i] = f2tf32(lin[((size_t)rel * CH + k) * CH + n] * (1.0f / 12.0f));
    }
}

extern "C" void kernel_launch(void* const* d_in, const int* in_sizes, int n_in,
                              void* d_out, int out_size)
{
    const float* x   = (const float*)d_in[0];
    const float* lin = (const float*)d_in[1];
    const void*  ptr = d_in[2];
    const void*  idx = d_in[3];
    const void*  et  = d_in[4];
    float* out = (float*)d_out;
    (void)in_sizes; (void)n_in; (void)out_size;

    cudaFuncSetAttribute(rgcn_kernel,
                         cudaFuncAttributeMaxDynamicSharedMemorySize, SMEM_BYTES);

    wt_kernel<<<(NREL * 8 * 4 * 32 * 4 + 255) / 256, 256>>>(lin);
    rgcn_kernel<<<GRID, THREADS, SMEM_BYTES>>>(x, ptr, idx, et, out);
}